// round 8
// baseline (speedup 1.0000x reference)
#include <cuda_runtime.h>
#include <math.h>

#define PI 3.141592653589793238462643383279502884

typedef unsigned long long u64;

// ---------------- f32x2 packed helpers ----------------
__device__ __forceinline__ u64 pk2(float lo, float hi) {
    u64 r;
    asm("mov.b64 %0, {%1, %2};" : "=l"(r) : "r"(__float_as_uint(lo)), "r"(__float_as_uint(hi)));
    return r;
}
__device__ __forceinline__ void up2(u64 v, float& lo, float& hi) {
    unsigned int a, b;
    asm("mov.b64 {%0, %1}, %2;" : "=r"(a), "=r"(b) : "l"(v));
    lo = __uint_as_float(a); hi = __uint_as_float(b);
}
__device__ __forceinline__ u64 fma2_(u64 a, u64 b, u64 c) {
    u64 d;
    asm("fma.rn.f32x2 %0, %1, %2, %3;" : "=l"(d) : "l"(a), "l"(b), "l"(c));
    return d;
}

// ---------------- constant/table device storage (no allocation allowed) ----------
__device__ double d_FACT[40], d_RFACT[40];
__device__ double d_w[64];
__device__ double d_chi[64], d_shi[64];
__device__ double d_cho[32], d_sho[32];
__device__ double d_chg[4],  d_shg[4];

__device__ float  g_W[64 * 16 * 16];
__device__ float  g_D2[31 * 31 * 32 * 16];
__device__ float2 g_FKc[32 * 16 * 31];
__device__ float2 g_EOUT[31 * 32];
__device__ float2 g_EIN16[16 * 64];
__device__ float2 g_EB[16 * 32];

__device__ float2 g_xm[8 * 64 * 16 * 64];
__device__ float2 g_xhat[16 * 128 * 64];
__device__ float2 g_khc[16 * 31 * 64 * 128];
__device__ float2 g_z[16 * 16 * 31 * 1024];
__device__ float2 g_fmn[32 * 256 * 16 * 124];

// ---------------- fp64 helpers ----------------
__device__ __forceinline__ double ipow(double x, int e) {
    double r = 1.0, b = x;
    while (e) { if (e & 1) r *= b; b *= b; e >>= 1; }
    return r;
}

__device__ double wig(int l, int m1, int m2, double ch, double sh) {
    int k0 = max(0, m2 - m1), k1 = min(l + m2, l - m1);
    if (k1 < k0) return 0.0;
    double num = sqrt(d_FACT[l + m1] * d_FACT[l - m1] * d_FACT[l + m2] * d_FACT[l - m2]);
    double cp = ipow(ch, 2 * l + m2 - m1 - 2 * k0);
    double sp = ipow(sh, m1 - m2 + 2 * k0);
    double c2i = 1.0 / (ch * ch), s2 = sh * sh;
    double sum = 0.0;
    for (int k = k0; k <= k1; ++k) {
        double t = num * d_RFACT[l + m2 - k] * d_RFACT[k] * d_RFACT[m1 - m2 + k] * d_RFACT[l - m1 - k] * cp * sp;
        sum += ((m1 - m2 + k) & 1) ? -t : t;
        cp *= c2i; sp *= s2;
    }
    return sum;
}

__device__ double wigD(int l, int m1, int m2, double ch, double sh) {
    int k0 = max(0, m2 - m1), k1 = min(l + m2, l - m1);
    if (k1 < k0) return 0.0;
    double num = sqrt(d_FACT[l + m1] * d_FACT[l - m1] * d_FACT[l + m2] * d_FACT[l - m2]);
    double ch2i = 1.0 / (ch * ch), sh2 = sh * sh;
    double ch4i = ch2i * ch2i, sh4 = sh2 * sh2;
    double cp0 = ipow(ch, 2 * l + m2 - m1 - 2 * k0);
    double sp0 = ipow(sh, m1 - m2 + 2 * k0);
    double cp1 = cp0 * ch2i, sp1 = sp0 * sh2;
    double s0 = 0.0, s1 = 0.0;
    int k = k0;
    for (; k + 1 <= k1; k += 2) {
        double t0 = num * d_RFACT[l + m2 - k] * d_RFACT[k] * d_RFACT[m1 - m2 + k] * d_RFACT[l - m1 - k];
        double t1 = num * d_RFACT[l + m2 - k - 1] * d_RFACT[k + 1] * d_RFACT[m1 - m2 + k + 1] * d_RFACT[l - m1 - k - 1];
        s0 += ((m1 - m2 + k) & 1) ? -(t0 * cp0 * sp0) : (t0 * cp0 * sp0);
        s1 += ((m1 - m2 + k + 1) & 1) ? -(t1 * cp1 * sp1) : (t1 * cp1 * sp1);
        cp0 *= ch4i; sp0 *= sh4; cp1 *= ch4i; sp1 *= sh4;
    }
    if (k <= k1) {
        double t0 = num * d_RFACT[l + m2 - k] * d_RFACT[k] * d_RFACT[m1 - m2 + k] * d_RFACT[l - m1 - k];
        s0 += ((m1 - m2 + k) & 1) ? -(t0 * cp0 * sp0) : (t0 * cp0 * sp0);
    }
    return s0 + s1;
}

// ---------------- P0: scalars + twiddle tables ----------------
__global__ void k_p0() {
    int t = threadIdx.x;
    if (t == 0) {
        double f = 1.0;
        d_FACT[0] = 1.0; d_RFACT[0] = 1.0;
        for (int n = 1; n < 40; ++n) { f *= (double)n; d_FACT[n] = f; d_RFACT[n] = 1.0 / f; }
    }
    if (t < 64) {
        double beta = PI * (2 * t + 0.5) / 128.0;
        d_chi[t] = cos(0.5 * beta); d_shi[t] = sin(0.5 * beta);
        double s = 0.0;
        for (int kk = 0; kk < 32; ++kk) s += sin(beta * (2 * kk + 1)) / (double)(2 * kk + 1);
        d_w[t] = (2.0 * PI / 64.0) * (2.0 / 32.0) * sin(beta) * s;
    }
    if (t < 32) {
        double beta = PI * (2 * t + 0.5) / 64.0;
        d_cho[t] = cos(0.5 * beta); d_sho[t] = sin(0.5 * beta);
    }
    if (t < 4) {
        double beta = (PI / 8.0) * (double)(t + 1) / 4.0;
        d_chg[t] = cos(0.5 * beta); d_shg[t] = sin(0.5 * beta);
    }
    for (int u = t; u < 16 * 64; u += 256) {
        int m = u >> 6, a = u & 63;
        double ang = -2.0 * PI * (double)m * (double)a / 64.0;
        g_EIN16[u] = make_float2((float)cos(ang), (float)sin(ang));
    }
    for (int u = t; u < 31 * 32; u += 256) {
        int nd = u >> 5, c = u & 31;
        double ang = 2.0 * PI * (double)(nd - 15) * (double)c / 32.0;
        g_EOUT[u] = make_float2((float)cos(ang), (float)sin(ang));
    }
    for (int u = t; u < 16 * 32; u += 256) {
        int mi = u >> 5, a = u & 31;
        double ang = 2.0 * PI * (double)mi * (double)a / 32.0;
        double sc = mi ? 2.0 : 1.0;
        g_EB[u] = make_float2((float)(sc * cos(ang)), (float)(sc * sin(ang)));
    }
}

// ---------------- K_TABF: W_ANA + FKc ----------------
__global__ void k_tabF() {
    int bx = blockIdx.x, t = threadIdx.x;
    if (bx < 64) {
        int idx = bx * 256 + t;
        int mi = idx & 15, l = (idx >> 4) & 15, j = idx >> 8;
        float v = 0.f;
        if (mi <= l) v = (float)(d_w[j] * wig(l, mi, 0, d_chi[j], d_shi[j]));
        g_W[idx] = v;
    } else {
        int idx = (bx - 64) * 256 + t;
        int md = idx % 31, l = (idx / 31) % 16, g = idx / 496;
        int m = md - 15;
        float2 v = make_float2(0.f, 0.f);
        if (m >= -l && m <= l) {
            int ib = g >> 3, ia = g & 7;
            double d = wig(l, m, 0, d_chg[ib], d_shg[ib]);
            double ang = (double)m * (2.0 * PI * (double)ia / 8.0);
            v = make_float2((float)(d * cos(ang)), (float)(-d * sin(ang)));
        }
        g_FKc[idx] = v;
    }
}

// ---------------- K_TABD: D2 table, warp-per-(m,nd,l), lane = beta ----------
__global__ void __launch_bounds__(256) k_tabD() {
    int w = blockIdx.x * 8 + (threadIdx.x >> 5);
    int lane = threadIdx.x & 31;
    int m = w / 496;
    int rem = w - m * 496;
    int nd = rem >> 4;
    int l = rem & 15;
    if (nd > 30) return;
    int n = nd - 15;
    if (m > l || abs(n) > l) return;
    if (n >= 0 && n > m) return;
    double d = (double)(2 * l + 1) * wigD(l, m, n, d_cho[lane], d_sho[lane]);
    float fd = (float)d;
    g_D2[(((m + 15) * 31 + nd) * 32 + lane) * 16 + l] = fd;
    if (n >= 0 && n < m) {
        float ds = ((m - n) & 1) ? -fd : fd;
        g_D2[(((n + 15) * 31 + (m + 15)) * 32 + lane) * 16 + l] = ds;
    }
}

// ---------------- KA1: alpha-DFT with alpha-parity fold ----------------
__global__ void __launch_bounds__(256) k_a1(const float* __restrict__ x) {
    __shared__ float xeS[64 * 33];
    __shared__ float xoS[64 * 33];
    __shared__ float2 eS[16 * 32];
    int b = blockIdx.x >> 6, jb = blockIdx.x & 63;
    int t = threadIdx.x;
    for (int u = t; u < 2048; u += 256) {
        int f = u >> 5, a = u & 31;
        const float* xp = x + ((b * 64 + f) * 64 + jb) * 64;
        float lo = xp[a], hi = xp[a + 32];
        xeS[f * 33 + a] = lo + hi;
        xoS[f * 33 + a] = lo - hi;
    }
    for (int u = t; u < 512; u += 256) {
        int m = u >> 5, a = u & 31;
        eS[u] = g_EIN16[m * 64 + a];
    }
    __syncthreads();
    int f = t & 63, mg = t >> 6;
    float2 acc[4];
#pragma unroll
    for (int j = 0; j < 4; ++j) acc[j] = make_float2(0.f, 0.f);
    const float* xe = &xeS[f * 33];
    const float* xo = &xoS[f * 33];
#pragma unroll 8
    for (int a = 0; a < 32; ++a) {
        float ve = xe[a], vo = xo[a];
#pragma unroll
        for (int j = 0; j < 4; ++j) {
            float v = (j & 1) ? vo : ve;
            float2 e = eS[(mg * 4 + j) * 32 + a];
            acc[j].x += v * e.x; acc[j].y += v * e.y;
        }
    }
#pragma unroll
    for (int j = 0; j < 4; ++j)
        g_xm[((b * 64 + jb) * 16 + mg * 4 + j) * 64 + f] = acc[j];
}

// ---------------- KA2: beta quadrature, 4-way j-split + smem reduce ------------
__global__ void __launch_bounds__(256) k_a2() {
    int mi = blockIdx.x, b = blockIdx.y;
    int t = threadIdx.x, f = t & 63, jh = t >> 6;
    __shared__ float Ws[64 * 16];
    __shared__ float2 red[3][16][64];
    for (int u = t; u < 1024; u += 256) {
        int j = u >> 4, l = u & 15;
        Ws[u] = g_W[(j * 16 + l) * 16 + mi];
    }
    __syncthreads();
    float2 acc[16];
#pragma unroll
    for (int l = 0; l < 16; ++l) acc[l] = make_float2(0.f, 0.f);
    for (int jj = 0; jj < 16; ++jj) {
        int j = jh * 16 + jj;
        float2 v = g_xm[((b * 64 + j) * 16 + mi) * 64 + f];
#pragma unroll
        for (int l = 0; l < 16; ++l) {
            float w = Ws[j * 16 + l];
            acc[l].x += w * v.x; acc[l].y += w * v.y;
        }
    }
    if (jh > 0) {
#pragma unroll
        for (int l = 0; l < 16; ++l) red[jh - 1][l][f] = acc[l];
    }
    __syncthreads();
    if (jh == 0) {
#pragma unroll
        for (int l = 0; l < 16; ++l) {
            float2 r0 = red[0][l][f], r1 = red[1][l][f], r2 = red[2][l][f];
            g_xhat[(l * 128 + mi * 8 + b) * 64 + f] =
                make_float2(acc[l].x + r0.x + r1.x + r2.x,
                            acc[l].y + r0.y + r1.y + r2.y);
        }
    }
}

// ---------------- KB: khc = conj(kh) ----------------
__global__ void __launch_bounds__(256) k_b(const float* __restrict__ ker) {
    __shared__ float ks[64 * 33];
    int i = blockIdx.x >> 1, half = blockIdx.x & 1;
    int t = threadIdx.x;
    for (int u = t; u < 2048; u += 256) {
        int ol = u >> 5, g = u & 31;
        ks[ol * 33 + g] = ker[(i * 128 + half * 64 + ol) * 32 + g];
    }
    __syncthreads();
    const float SC = 0.002762135864009951f;
    int ol = t & 63, pg = t >> 6;
    for (int it = 0; it < 64; ++it) {
        int p = it * 4 + pg;
        int l = (int)floorf(sqrtf((float)p + 0.5f));
        int nd = 15 - l + (p - l * l);
        float2 acc = make_float2(0.f, 0.f);
#pragma unroll 8
        for (int g = 0; g < 32; ++g) {
            float kv = ks[ol * 33 + g];
            float2 fv = g_FKc[(g * 16 + l) * 31 + nd];
            acc.x += kv * fv.x; acc.y += kv * fv.y;
        }
        g_khc[((l * 31 + nd) * 64 + i) * 128 + half * 64 + ol] =
            make_float2(SC * acc.x, SC * acc.y);
    }
}

// ---------------- KC: per-degree complex GEMM, f32x2 packed ----------
__global__ void __launch_bounds__(256) k_c() {
    int l = blockIdx.z;
    int rows = (l + 1) * 8;
    int nT = (2 * l + 1) * 2;
    if ((int)blockIdx.x >= nT) return;
    int row0 = blockIdx.y * 64;
    if (row0 >= rows) return;
    int ndi = blockIdx.x >> 1;
    int o0 = (blockIdx.x & 1) * 64;
    int nd = 15 - l + ndi;
    __shared__ u64 Asx[16 * 65];   // (a.x, a.x)
    __shared__ u64 Asn[16 * 65];   // (-a.y, a.y)
    __shared__ u64 Bn[16 * 64];    // (b.x, b.y)
    __shared__ u64 Bsw[16 * 64];   // (b.y, b.x)
    int t = threadIdx.x, tx = t & 15, ty = t >> 4;
    u64 acc[4][4];
#pragma unroll
    for (int i = 0; i < 4; ++i)
#pragma unroll
        for (int j = 0; j < 4; ++j) acc[i][j] = 0ull;
    const u64* khu = (const u64*)g_khc;
    for (int kc = 0; kc < 64; kc += 16) {
        {
            int kk = t & 15, r0 = t >> 4;
#pragma unroll
            for (int p = 0; p < 4; ++p) {
                float2 a = g_xhat[(l * 128 + row0 + r0 + 16 * p) * 64 + kc + kk];
                Asx[kk * 65 + r0 + 16 * p] = pk2(a.x, a.x);
                Asn[kk * 65 + r0 + 16 * p] = pk2(-a.y, a.y);
            }
        }
        {
            int cc = t & 63, kb = t >> 6;
#pragma unroll
            for (int p = 0; p < 4; ++p) {
                u64 bvu = khu[((size_t)(l * 31 + nd) * 64 + kc + kb + 4 * p) * 128 + o0 + cc];
                Bn[(kb + 4 * p) * 64 + cc] = bvu;
                float bx, by; up2(bvu, bx, by);
                Bsw[(kb + 4 * p) * 64 + cc] = pk2(by, bx);
            }
        }
        __syncthreads();
#pragma unroll
        for (int kk = 0; kk < 16; ++kk) {
            u64 ax[4], an[4], bn_[4], bw[4];
#pragma unroll
            for (int i = 0; i < 4; ++i) {
                ax[i] = Asx[kk * 65 + ty + 16 * i];
                an[i] = Asn[kk * 65 + ty + 16 * i];
            }
#pragma unroll
            for (int j = 0; j < 4; ++j) {
                bn_[j] = Bn[kk * 64 + tx + 16 * j];
                bw[j] = Bsw[kk * 64 + tx + 16 * j];
            }
#pragma unroll
            for (int i = 0; i < 4; ++i)
#pragma unroll
                for (int j = 0; j < 4; ++j) {
                    acc[i][j] = fma2_(ax[i], bn_[j], acc[i][j]);
                    acc[i][j] = fma2_(an[i], bw[j], acc[i][j]);
                }
        }
        __syncthreads();
    }
    u64* zu = (u64*)g_z;
#pragma unroll
    for (int i = 0; i < 4; ++i) {
        int R = row0 + ty + 16 * i;
        if (R < rows) {
            int base = ((l * 16 + (R >> 3)) * 31 + nd) * 1024 + (R & 7) * 128 + o0;
#pragma unroll
            for (int j = 0; j < 4; ++j) zu[base + tx + 16 * j] = acc[i][j];
        }
    }
}

// ---------------- KD: fmn = sum_l D2 * z, f32x2 packed -------------
template<int LMIN>
__device__ __forceinline__ void kd_body(const u64* __restrict__ Dsx,
                                        int bo0, int nd, int mi, int t) {
    constexpr int NLz = 16 - LMIN;
    const u64* zu = (const u64*)g_z;
    u64 zr[NLz];
#pragma unroll
    for (int u = 0; u < NLz; ++u)
        zr[u] = zu[(((size_t)(LMIN + u) * 16 + mi) * 31 + nd) * 1024 + bo0 + t];
    int bo = bo0 + t;
    int baseq = ((bo >> 2) * 16 + mi) * 124 + nd * 4 + (bo & 3);
    u64* fu = (u64*)g_fmn;
    for (int k = 0; k < 32; ++k) {
        u64 acc = 0ull;
#pragma unroll
        for (int u = 0; u < NLz; ++u)
            acc = fma2_(Dsx[k * 16 + LMIN + u], zr[u], acc);
        fu[(size_t)k * 507904 + baseq] = acc;
    }
}

__global__ void __launch_bounds__(256) k_d() {
    int bo0 = blockIdx.x * 256, nd = blockIdx.y, mi = blockIdx.z;
    int t = threadIdx.x;
    int n = nd - 15;
    int lmin = max(mi, abs(n));
    __shared__ u64 Dsx[512];
    for (int u = t; u < 512; u += 256) {
        float d = g_D2[((mi + 15) * 31 + nd) * 512 + u];
        Dsx[u] = pk2(d, d);
    }
    __syncthreads();
    switch (lmin) {
        case 0:  kd_body<0>(Dsx, bo0, nd, mi, t);  break;
        case 1:  kd_body<1>(Dsx, bo0, nd, mi, t);  break;
        case 2:  kd_body<2>(Dsx, bo0, nd, mi, t);  break;
        case 3:  kd_body<3>(Dsx, bo0, nd, mi, t);  break;
        case 4:  kd_body<4>(Dsx, bo0, nd, mi, t);  break;
        case 5:  kd_body<5>(Dsx, bo0, nd, mi, t);  break;
        case 6:  kd_body<6>(Dsx, bo0, nd, mi, t);  break;
        case 7:  kd_body<7>(Dsx, bo0, nd, mi, t);  break;
        case 8:  kd_body<8>(Dsx, bo0, nd, mi, t);  break;
        case 9:  kd_body<9>(Dsx, bo0, nd, mi, t);  break;
        case 10: kd_body<10>(Dsx, bo0, nd, mi, t); break;
        case 11: kd_body<11>(Dsx, bo0, nd, mi, t); break;
        case 12: kd_body<12>(Dsx, bo0, nd, mi, t); break;
        case 13: kd_body<13>(Dsx, bo0, nd, mi, t); break;
        case 14: kd_body<14>(Dsx, bo0, nd, mi, t); break;
        default: kd_body<15>(Dsx, bo0, nd, mi, t); break;
    }
}

// ---------------- KEF: fused n-DFT + real m-DFT, f32x2 packed ----------------
__global__ void __launch_bounds__(256) k_ef(float* __restrict__ out, const float* __restrict__ bias) {
    int boq = blockIdx.x, k = blockIdx.y;
    // sbuf: stage1 f-broadcast tables; reused for Hs after stage1
    __shared__ __align__(16) u64 sbuf[3968];        // bufX [0,1984), bufY [1984,3968)
    __shared__ __align__(16) float2 ES1[31 * 16];   // (e.x, e.y)
    __shared__ u64 ESn[31 * 16];                    // (-e.y, e.x)
    __shared__ __align__(16) ulonglong2 EBp[128];   // [mi][jpg]: ((e0.x,e1.x),(-e0.y,-e1.y))
    int t = threadIdx.x;
    u64* bufX = sbuf;
    u64* bufY = sbuf + 1984;
    {
        const float4* src = (const float4*)(g_fmn + (size_t)(k * 256 + boq) * 1984);
        for (int u = t; u < 992; u += 256) {
            float4 v = src[u];
            bufX[2 * u]     = pk2(v.x, v.x);
            bufY[2 * u]     = pk2(v.y, v.y);
            bufX[2 * u + 1] = pk2(v.z, v.z);
            bufY[2 * u + 1] = pk2(v.w, v.w);
        }
    }
    for (int u = t; u < 496; u += 256) {
        int nd = u >> 4, c = u & 15;
        float2 e = g_EOUT[nd * 32 + c];
        ES1[u] = e;
        ESn[u] = pk2(-e.y, e.x);
    }
    for (int u = t; u < 128; u += 256) {
        int mi = u >> 3, jpg = u & 7;
        float2 e0 = g_EB[mi * 32 + 2 * jpg];
        float2 e1 = g_EB[mi * 32 + 2 * jpg + 1];
        EBp[u] = make_ulonglong2(pk2(e0.x, e1.x), pk2(-e0.y, -e1.y));
    }
    __syncthreads();
    // stage 1: H[mi][c] = sum_nd f * e, c+16 via n-parity; packed (re, im)
    u64 uE[4], uO[4];
    {
        int mi = t >> 4, c = t & 15;
#pragma unroll
        for (int q = 0; q < 4; ++q) { uE[q] = 0ull; uO[q] = 0ull; }
        const u64* ES1u = (const u64*)ES1;
#pragma unroll
        for (int nd = 0; nd < 31; ++nd) {
            u64 ep = ES1u[nd * 16 + c];
            u64 en = ESn[nd * 16 + c];
            const ulonglong2* fx = (const ulonglong2*)&bufX[mi * 124 + nd * 4];
            const ulonglong2* fy = (const ulonglong2*)&bufY[mi * 124 + nd * 4];
            ulonglong2 fxa = fx[0], fxb = fx[1];
            ulonglong2 fya = fy[0], fyb = fy[1];
            if (nd & 1) {   // n = nd-15 even
                uE[0] = fma2_(fxa.x, ep, uE[0]); uE[0] = fma2_(fya.x, en, uE[0]);
                uE[1] = fma2_(fxa.y, ep, uE[1]); uE[1] = fma2_(fya.y, en, uE[1]);
                uE[2] = fma2_(fxb.x, ep, uE[2]); uE[2] = fma2_(fyb.x, en, uE[2]);
                uE[3] = fma2_(fxb.y, ep, uE[3]); uE[3] = fma2_(fyb.y, en, uE[3]);
            } else {
                uO[0] = fma2_(fxa.x, ep, uO[0]); uO[0] = fma2_(fya.x, en, uO[0]);
                uO[1] = fma2_(fxa.y, ep, uO[1]); uO[1] = fma2_(fya.y, en, uO[1]);
                uO[2] = fma2_(fxb.x, ep, uO[2]); uO[2] = fma2_(fyb.x, en, uO[2]);
                uO[3] = fma2_(fxb.y, ep, uO[3]); uO[3] = fma2_(fyb.y, en, uO[3]);
            }
        }
    }
    __syncthreads();    // everyone done reading bufX/bufY
    float2* Hs = (float2*)sbuf;     // 2048 float2 = 16KB, reuses f-table region
    {
        int mi = t >> 4, c = t & 15;
#pragma unroll
        for (int q = 0; q < 4; ++q) {
            float Ex, Ey, Ox, Oy;
            up2(uE[q], Ex, Ey);
            up2(uO[q], Ox, Oy);
            Hs[(q * 16 + mi) * 32 + c]      = make_float2(Ex + Ox, Ey + Oy);
            Hs[(q * 16 + mi) * 32 + c + 16] = make_float2(Ex - Ox, Ey - Oy);
        }
    }
    __syncthreads();
    // stage 2: out[a][c] = sum_mi Re(w_mi H e^{i2pi mi a/32}); a+16 via m-parity
    {
        int c2 = t & 31, q = (t >> 5) & 3, ag = t >> 7;
        u64 Ep[4], Op[4];
#pragma unroll
        for (int jp = 0; jp < 4; ++jp) { Ep[jp] = 0ull; Op[jp] = 0ull; }
#pragma unroll
        for (int mi = 0; mi < 16; ++mi) {
            float2 h = Hs[(q * 16 + mi) * 32 + c2];
            u64 hxx = pk2(h.x, h.x);
            u64 hyy = pk2(h.y, h.y);
            const ulonglong2* eb = &EBp[mi * 8 + ag * 4];
            if (mi & 1) {
#pragma unroll
                for (int jp = 0; jp < 4; ++jp) {
                    ulonglong2 e2 = eb[jp];
                    Op[jp] = fma2_(hxx, e2.x, Op[jp]);
                    Op[jp] = fma2_(hyy, e2.y, Op[jp]);
                }
            } else {
#pragma unroll
                for (int jp = 0; jp < 4; ++jp) {
                    ulonglong2 e2 = eb[jp];
                    Ep[jp] = fma2_(hxx, e2.x, Ep[jp]);
                    Ep[jp] = fma2_(hyy, e2.y, Ep[jp]);
                }
            }
        }
        int bo = boq * 4 + q;
        float bv = bias[bo & 127];
        size_t base = ((size_t)(bo * 32 + k)) * 1024 + c2;
#pragma unroll
        for (int jp = 0; jp < 4; ++jp) {
            float E0, E1, O0, O1;
            up2(Ep[jp], E0, E1);
            up2(Op[jp], O0, O1);
            int a0 = ag * 8 + 2 * jp;
            out[base + a0 * 32]        = E0 + O0 + bv;
            out[base + (a0 + 16) * 32] = E0 - O0 + bv;
            out[base + (a0 + 1) * 32]  = E1 + O1 + bv;
            out[base + (a0 + 17) * 32] = E1 - O1 + bv;
        }
    }
}

// ---------------- stream/event fork-join (created at static init) -------------
static cudaStream_t g_s1 = 0;
static cudaEvent_t g_eP0 = 0, g_eTabF = 0, g_eA2 = 0;
static bool g_streamOK = false;
namespace {
struct StreamInit {
    StreamInit() {
        bool ok = (cudaStreamCreateWithFlags(&g_s1, cudaStreamNonBlocking) == cudaSuccess);
        ok = ok && (cudaEventCreateWithFlags(&g_eP0, cudaEventDisableTiming) == cudaSuccess);
        ok = ok && (cudaEventCreateWithFlags(&g_eTabF, cudaEventDisableTiming) == cudaSuccess);
        ok = ok && (cudaEventCreateWithFlags(&g_eA2, cudaEventDisableTiming) == cudaSuccess);
        g_streamOK = ok;
    }
};
static StreamInit g_streamInit;
}

// ---------------- launch ----------------
extern "C" void kernel_launch(void* const* d_in, const int* in_sizes, int n_in,
                              void* d_out, int out_size) {
    const float* x    = (const float*)d_in[0];
    const float* ker  = (const float*)d_in[1];
    const float* bias = (const float*)d_in[2];
    float* out = (float*)d_out;

    if (g_streamOK) {
        k_p0<<<1, 256>>>();
        cudaEventRecord(g_eP0, 0);
        // side stream: input alpha-DFT, then beta quadrature (after tabF for g_W)
        cudaStreamWaitEvent(g_s1, g_eP0, 0);
        k_a1<<<512, 256, 0, g_s1>>>(x);
        // main: W + FKc, then D2 + kernel SH expansion
        k_tabF<<<126, 256>>>();
        cudaEventRecord(g_eTabF, 0);
        cudaStreamWaitEvent(g_s1, g_eTabF, 0);
        k_a2<<<dim3(16, 8), 256, 0, g_s1>>>();
        cudaEventRecord(g_eA2, g_s1);
        k_tabD<<<992, 256>>>();
        k_b<<<128, 256>>>(ker);
        cudaStreamWaitEvent(0, g_eA2, 0);
        k_c<<<dim3(62, 2, 16), 256>>>();
        k_d<<<dim3(4, 31, 16), 256>>>();
        k_ef<<<dim3(256, 32), 256>>>(out, bias);
    } else {
        k_p0<<<1, 256>>>();
        k_tabF<<<126, 256>>>();
        k_tabD<<<992, 256>>>();
        k_a1<<<512, 256>>>(x);
        k_a2<<<dim3(16, 8), 256>>>();
        k_b<<<128, 256>>>(ker);
        k_c<<<dim3(62, 2, 16), 256>>>();
        k_d<<<dim3(4, 31, 16), 256>>>();
        k_ef<<<dim3(256, 32), 256>>>(out, bias);
    }
    (void)in_sizes; (void)n_in; (void)out_size;
}

// round 9
// speedup vs baseline: 1.1543x; 1.1543x over previous
#include <cuda_runtime.h>
#include <math.h>

#define PI 3.141592653589793238462643383279502884

// ---------------- constant/table device storage (no allocation allowed) ----------
__device__ double d_FACT[40], d_RFACT[40];
__device__ double d_w[64];
__device__ double d_chi[64], d_shi[64];   // half-angle trig, input betas
__device__ double d_cho[32], d_sho[32];   // output betas
__device__ double d_chg[4],  d_shg[4];    // kernel-grid betas

__device__ float  g_W[64 * 16 * 16];          // [j][l][mi] = w_j d^l_{m,0}(beta_in_j), m>=0
__device__ float  g_D2[31 * 31 * 32 * 16];    // [md][nd][k][l]; only md>=15 rows written
__device__ float2 g_FKc[32 * 16 * 31];        // conj(FK) [g][l][md]
__device__ float2 g_EOUT[31 * 32];            // e^{+2pi i n c/32}   [nd][c]
__device__ float2 g_EIN16[16 * 64];           // e^{-2pi i m a/64}   [m][a], m>=0
__device__ float2 g_EB[16 * 32];              // (m?2:1) e^{+2pi i m a/32} [mi][a]

__device__ float2 g_xm[8 * 64 * 16 * 64];     // [b][j][mi][f]
__device__ float2 g_xhat[16 * 128 * 64];      // [l][(mi*8+b)][f]
__device__ float2 g_khc[16 * 31 * 64 * 128];  // [l][nd][i][o]
__device__ float2 g_z[16 * 16 * 31 * 1024];   // [l][mi][nd][bo]
__device__ float2 g_fmn[32 * 256 * 16 * 124]; // [k][boq][mi][nd*4+q]

// ---------------- helpers ----------------
__device__ __forceinline__ double ipow(double x, int e) {
    double r = 1.0, b = x;
    while (e) { if (e & 1) r *= b; b *= b; e >>= 1; }
    return r;
}

// Wigner small-d with factorial tables staged in shared memory
__device__ double wigS(int l, int m1, int m2, double ch, double sh,
                       const double* __restrict__ sF, const double* __restrict__ sRF) {
    int k0 = max(0, m2 - m1), k1 = min(l + m2, l - m1);
    if (k1 < k0) return 0.0;
    double num = sqrt(sF[l + m1] * sF[l - m1] * sF[l + m2] * sF[l - m2]);
    double cp = ipow(ch, 2 * l + m2 - m1 - 2 * k0);
    double sp = ipow(sh, m1 - m2 + 2 * k0);
    double c2i = 1.0 / (ch * ch), s2 = sh * sh;
    double sum = 0.0;
    for (int k = k0; k <= k1; ++k) {
        double t = num * sRF[l + m2 - k] * sRF[k] * sRF[m1 - m2 + k] * sRF[l - m1 - k] * cp * sp;
        sum += ((m1 - m2 + k) & 1) ? -t : t;
        cp *= c2i; sp *= s2;
    }
    return sum;
}

__device__ __forceinline__ void cfma(float2& c, float2 a, float2 b) {
    c.x += a.x * b.x - a.y * b.y;
    c.y += a.x * b.y + a.y * b.x;
}

// ---------------- P0: scalars + twiddle tables ----------------
__global__ void k_p0() {
    int t = threadIdx.x;
    if (t == 0) {
        double f = 1.0;
        d_FACT[0] = 1.0; d_RFACT[0] = 1.0;
        for (int n = 1; n < 40; ++n) { f *= (double)n; d_FACT[n] = f; d_RFACT[n] = 1.0 / f; }
    }
    if (t < 64) {
        double beta = PI * (2 * t + 0.5) / 128.0;
        d_chi[t] = cos(0.5 * beta); d_shi[t] = sin(0.5 * beta);
        double s = 0.0;
        for (int kk = 0; kk < 32; ++kk) s += sin(beta * (2 * kk + 1)) / (double)(2 * kk + 1);
        d_w[t] = (2.0 * PI / 64.0) * (2.0 / 32.0) * sin(beta) * s;
    }
    if (t < 32) {
        double beta = PI * (2 * t + 0.5) / 64.0;
        d_cho[t] = cos(0.5 * beta); d_sho[t] = sin(0.5 * beta);
    }
    if (t < 4) {
        double beta = (PI / 8.0) * (double)(t + 1) / 4.0;
        d_chg[t] = cos(0.5 * beta); d_shg[t] = sin(0.5 * beta);
    }
    for (int u = t; u < 16 * 64; u += 256) {
        int m = u >> 6, a = u & 63;
        double ang = -2.0 * PI * (double)m * (double)a / 64.0;
        g_EIN16[u] = make_float2((float)cos(ang), (float)sin(ang));
    }
    for (int u = t; u < 31 * 32; u += 256) {
        int nd = u >> 5, c = u & 31;
        double ang = 2.0 * PI * (double)(nd - 15) * (double)c / 32.0;
        g_EOUT[u] = make_float2((float)cos(ang), (float)sin(ang));
    }
    for (int u = t; u < 16 * 32; u += 256) {
        int mi = u >> 5, a = u & 31;
        double ang = 2.0 * PI * (double)mi * (double)a / 32.0;
        double sc = mi ? 2.0 : 1.0;
        g_EB[u] = make_float2((float)(sc * cos(ang)), (float)(sc * sin(ang)));
    }
}

// ---------------- K_TABF: W_ANA + FKc (fast path tables) ----------------
__global__ void k_tabF() {
    __shared__ double sF[40], sRF[40];
    int bx = blockIdx.x, t = threadIdx.x;
    if (t < 40) { sF[t] = d_FACT[t]; sRF[t] = d_RFACT[t]; }
    __syncthreads();
    if (bx < 64) {
        int idx = bx * 256 + t;
        int mi = idx & 15, l = (idx >> 4) & 15, j = idx >> 8;
        float v = 0.f;
        if (mi <= l) v = (float)(d_w[j] * wigS(l, mi, 0, d_chi[j], d_shi[j], sF, sRF));
        g_W[idx] = v;
    } else {
        int idx = (bx - 64) * 256 + t;
        int md = idx % 31, l = (idx / 31) % 16, g = idx / 496;
        int m = md - 15;
        float2 v = make_float2(0.f, 0.f);
        if (m >= -l && m <= l) {
            int ib = g >> 3, ia = g & 7;
            double d = wigS(l, m, 0, d_chg[ib], d_shg[ib], sF, sRF);
            double ang = (double)m * (2.0 * PI * (double)ia / 8.0);
            v = make_float2((float)(d * cos(ang)), (float)(-d * sin(ang)));
        }
        g_FKc[idx] = v;
    }
}

// ---------------- K_TABD: D2 table, warp-per-(m,nd,l), lane = beta ----------
__global__ void __launch_bounds__(256) k_tabD() {
    __shared__ double sF[40], sRF[40], sch[32], ssh[32];
    int t = threadIdx.x;
    if (t < 40) { sF[t] = d_FACT[t]; sRF[t] = d_RFACT[t]; }
    if (t >= 64 && t < 96)  sch[t - 64] = d_cho[t - 64];
    if (t >= 96 && t < 128) ssh[t - 96] = d_sho[t - 96];
    __syncthreads();
    int w = blockIdx.x * 8 + (t >> 5);
    int lane = t & 31;
    int m = w / 496;
    int rem = w - m * 496;
    int nd = rem >> 4;     // 0..30
    int l = rem & 15;
    int n = nd - 15;
    if (m > l || abs(n) > l) return;
    if (n >= 0 && n > m) return;     // covered by (n,m) thread
    double d = (double)(2 * l + 1) * wigS(l, m, n, sch[lane], ssh[lane], sF, sRF);
    float fd = (float)d;
    g_D2[(((m + 15) * 31 + nd) * 32 + lane) * 16 + l] = fd;
    if (n >= 0 && n < m) {
        float ds = ((m - n) & 1) ? -fd : fd;   // d^l_{n,m} = (-1)^{m-n} d^l_{m,n}
        g_D2[(((n + 15) * 31 + (m + 15)) * 32 + lane) * 16 + l] = ds;
    }
}

// ---------------- KA1: alpha-DFT with alpha-parity fold ----------------
__global__ void __launch_bounds__(256) k_a1(const float* __restrict__ x) {
    __shared__ float xeS[64 * 33];
    __shared__ float xoS[64 * 33];
    __shared__ float2 eS[16 * 32];
    int b = blockIdx.x >> 6, jb = blockIdx.x & 63;
    int t = threadIdx.x;
    for (int u = t; u < 2048; u += 256) {
        int f = u >> 5, a = u & 31;
        const float* xp = x + ((b * 64 + f) * 64 + jb) * 64;
        float lo = xp[a], hi = xp[a + 32];
        xeS[f * 33 + a] = lo + hi;
        xoS[f * 33 + a] = lo - hi;
    }
    for (int u = t; u < 512; u += 256) {
        int m = u >> 5, a = u & 31;
        eS[u] = g_EIN16[m * 64 + a];
    }
    __syncthreads();
    int f = t & 63, mg = t >> 6;
    float2 acc[4];
#pragma unroll
    for (int j = 0; j < 4; ++j) acc[j] = make_float2(0.f, 0.f);
    const float* xe = &xeS[f * 33];
    const float* xo = &xoS[f * 33];
#pragma unroll 8
    for (int a = 0; a < 32; ++a) {
        float ve = xe[a], vo = xo[a];
#pragma unroll
        for (int j = 0; j < 4; ++j) {
            float v = (j & 1) ? vo : ve;
            float2 e = eS[(mg * 4 + j) * 32 + a];
            acc[j].x += v * e.x; acc[j].y += v * e.y;
        }
    }
#pragma unroll
    for (int j = 0; j < 4; ++j)
        g_xm[((b * 64 + jb) * 16 + mg * 4 + j) * 64 + f] = acc[j];
}

// ---------------- KA2: beta quadrature, 4-way j-split + smem reduce ------------
__global__ void __launch_bounds__(256) k_a2() {
    int mi = blockIdx.x, b = blockIdx.y;
    int t = threadIdx.x, f = t & 63, jh = t >> 6;
    __shared__ float Ws[64 * 16];
    __shared__ float2 red[3][16][64];
    for (int u = t; u < 1024; u += 256) {
        int j = u >> 4, l = u & 15;
        Ws[u] = g_W[(j * 16 + l) * 16 + mi];
    }
    __syncthreads();
    float2 acc[16];
#pragma unroll
    for (int l = 0; l < 16; ++l) acc[l] = make_float2(0.f, 0.f);
    for (int jj = 0; jj < 16; ++jj) {
        int j = jh * 16 + jj;
        float2 v = g_xm[((b * 64 + j) * 16 + mi) * 64 + f];
#pragma unroll
        for (int l = 0; l < 16; ++l) {
            float w = Ws[j * 16 + l];
            acc[l].x += w * v.x; acc[l].y += w * v.y;
        }
    }
    if (jh > 0) {
#pragma unroll
        for (int l = 0; l < 16; ++l) red[jh - 1][l][f] = acc[l];
    }
    __syncthreads();
    if (jh == 0) {
#pragma unroll
        for (int l = 0; l < 16; ++l) {
            float2 r0 = red[0][l][f], r1 = red[1][l][f], r2 = red[2][l][f];
            g_xhat[(l * 128 + mi * 8 + b) * 64 + f] =
                make_float2(acc[l].x + r0.x + r1.x + r2.x,
                            acc[l].y + r0.y + r1.y + r2.y);
        }
    }
}

// ---------------- KB: khc = conj(kh) ----------------
__global__ void __launch_bounds__(256) k_b(const float* __restrict__ ker) {
    __shared__ float ks[64 * 33];
    int i = blockIdx.x >> 1, half = blockIdx.x & 1;
    int t = threadIdx.x;
    for (int u = t; u < 2048; u += 256) {
        int ol = u >> 5, g = u & 31;
        ks[ol * 33 + g] = ker[(i * 128 + half * 64 + ol) * 32 + g];
    }
    __syncthreads();
    const float SC = 0.002762135864009951f;   // 1/sqrt(131072)
    int ol = t & 63, pg = t >> 6;
    for (int it = 0; it < 64; ++it) {
        int p = it * 4 + pg;
        int l = (int)floorf(sqrtf((float)p + 0.5f));
        int nd = 15 - l + (p - l * l);
        float2 acc = make_float2(0.f, 0.f);
#pragma unroll 8
        for (int g = 0; g < 32; ++g) {
            float kv = ks[ol * 33 + g];
            float2 fv = g_FKc[(g * 16 + l) * 31 + nd];
            acc.x += kv * fv.x; acc.y += kv * fv.y;
        }
        g_khc[((l * 31 + nd) * 64 + i) * 128 + half * 64 + ol] =
            make_float2(SC * acc.x, SC * acc.y);
    }
}

// ---------------- KC: per-degree complex GEMM, 64x64 tile, 4x4 micro ----------
__global__ void __launch_bounds__(256) k_c() {
    int l = blockIdx.z;
    int rows = (l + 1) * 8;
    int nT = (2 * l + 1) * 2;
    if ((int)blockIdx.x >= nT) return;
    int row0 = blockIdx.y * 64;
    if (row0 >= rows) return;
    int ndi = blockIdx.x >> 1;
    int o0 = (blockIdx.x & 1) * 64;
    int nd = 15 - l + ndi;
    __shared__ float2 As[16 * 65];
    __shared__ float2 Bs[16 * 64];
    int t = threadIdx.x, tx = t & 15, ty = t >> 4;
    float2 c[4][4] = {};
    for (int kc = 0; kc < 64; kc += 16) {
        {
            int kk = t & 15, r0 = t >> 4;
#pragma unroll
            for (int p = 0; p < 4; ++p)
                As[kk * 65 + r0 + 16 * p] = g_xhat[(l * 128 + row0 + r0 + 16 * p) * 64 + kc + kk];
        }
        {
            int cc = t & 63, kb = t >> 6;
#pragma unroll
            for (int p = 0; p < 4; ++p)
                Bs[(kb + 4 * p) * 64 + cc] = g_khc[((l * 31 + nd) * 64 + kc + kb + 4 * p) * 128 + o0 + cc];
        }
        __syncthreads();
#pragma unroll
        for (int kk = 0; kk < 16; ++kk) {
            float2 a[4], bv[4];
#pragma unroll
            for (int i = 0; i < 4; ++i) a[i] = As[kk * 65 + ty + 16 * i];
#pragma unroll
            for (int j = 0; j < 4; ++j) bv[j] = Bs[kk * 64 + tx + 16 * j];
#pragma unroll
            for (int i = 0; i < 4; ++i)
#pragma unroll
                for (int j = 0; j < 4; ++j) cfma(c[i][j], a[i], bv[j]);
        }
        __syncthreads();
    }
#pragma unroll
    for (int i = 0; i < 4; ++i) {
        int R = row0 + ty + 16 * i;
        if (R < rows) {
            int base = ((l * 16 + (R >> 3)) * 31 + nd) * 1024 + (R & 7) * 128 + o0;
#pragma unroll
            for (int j = 0; j < 4; ++j) g_z[base + tx + 16 * j] = c[i][j];
        }
    }
}

// ---------------- KD: fmn = sum_l D2 * z, lmin-templated sparsity -------------
template<int LMIN>
__device__ __forceinline__ void kd_body(const float* __restrict__ Ds,
                                        int bo0, int nd, int mi, int t) {
    constexpr int NLz = 16 - LMIN;
    float2 zr[NLz];
#pragma unroll
    for (int u = 0; u < NLz; ++u)
        zr[u] = g_z[(((LMIN + u) * 16 + mi) * 31 + nd) * 1024 + bo0 + t];
    int bo = bo0 + t;
    int baseq = ((bo >> 2) * 16 + mi) * 124 + nd * 4 + (bo & 3);
    for (int k = 0; k < 32; ++k) {
        float2 acc = make_float2(0.f, 0.f);
#pragma unroll
        for (int u = 0; u < NLz; ++u) {
            float d = Ds[k * 16 + LMIN + u];
            acc.x += d * zr[u].x; acc.y += d * zr[u].y;
        }
        g_fmn[k * 507904 + baseq] = acc;
    }
}

__global__ void __launch_bounds__(256) k_d() {
    int bo0 = blockIdx.x * 256, nd = blockIdx.y, mi = blockIdx.z;
    int t = threadIdx.x;
    int n = nd - 15;
    int lmin = max(mi, abs(n));
    __shared__ float Ds[512];
    for (int u = t; u < 512; u += 256)
        Ds[u] = g_D2[((mi + 15) * 31 + nd) * 512 + u];
    __syncthreads();
    switch (lmin) {
        case 0:  kd_body<0>(Ds, bo0, nd, mi, t);  break;
        case 1:  kd_body<1>(Ds, bo0, nd, mi, t);  break;
        case 2:  kd_body<2>(Ds, bo0, nd, mi, t);  break;
        case 3:  kd_body<3>(Ds, bo0, nd, mi, t);  break;
        case 4:  kd_body<4>(Ds, bo0, nd, mi, t);  break;
        case 5:  kd_body<5>(Ds, bo0, nd, mi, t);  break;
        case 6:  kd_body<6>(Ds, bo0, nd, mi, t);  break;
        case 7:  kd_body<7>(Ds, bo0, nd, mi, t);  break;
        case 8:  kd_body<8>(Ds, bo0, nd, mi, t);  break;
        case 9:  kd_body<9>(Ds, bo0, nd, mi, t);  break;
        case 10: kd_body<10>(Ds, bo0, nd, mi, t); break;
        case 11: kd_body<11>(Ds, bo0, nd, mi, t); break;
        case 12: kd_body<12>(Ds, bo0, nd, mi, t); break;
        case 13: kd_body<13>(Ds, bo0, nd, mi, t); break;
        case 14: kd_body<14>(Ds, bo0, nd, mi, t); break;
        default: kd_body<15>(Ds, bo0, nd, mi, t); break;
    }
}

// ---------------- KEF: fused n-DFT + real m-DFT, table twiddles ----------------
__global__ void __launch_bounds__(256) k_ef(float* __restrict__ out, const float* __restrict__ bias) {
    int boq = blockIdx.x, k = blockIdx.y;
    __shared__ __align__(16) float2 fS[16 * 124];
    __shared__ float2 Hs[4 * 16 * 32];
    __shared__ float2 ES1[31 * 16];
    __shared__ float2 EBs[16 * 32];
    int t = threadIdx.x;
    {
        const float4* src = (const float4*)(g_fmn + (size_t)(k * 256 + boq) * 1984);
        float4* dst = (float4*)fS;
        for (int u = t; u < 992; u += 256) dst[u] = src[u];
    }
    for (int u = t; u < 496; u += 256) {
        int nd = u >> 4, c = u & 15;
        ES1[u] = g_EOUT[nd * 32 + c];
    }
    for (int u = t; u < 512; u += 256) EBs[u] = g_EB[u];
    __syncthreads();
    {
        int mi = t >> 4, c = t & 15;
        float2 E[4], O[4];
#pragma unroll
        for (int q = 0; q < 4; ++q) { E[q] = make_float2(0.f, 0.f); O[q] = make_float2(0.f, 0.f); }
        const float4* f4 = (const float4*)(fS + mi * 124);
#pragma unroll
        for (int nd = 0; nd < 31; ++nd) {
            float2 e = ES1[nd * 16 + c];
            float4 lo = f4[nd * 2], hi = f4[nd * 2 + 1];
            float2 f0 = make_float2(lo.x, lo.y), f1 = make_float2(lo.z, lo.w);
            float2 f2 = make_float2(hi.x, hi.y), f3 = make_float2(hi.z, hi.w);
            if (nd & 1) {
                cfma(E[0], f0, e); cfma(E[1], f1, e); cfma(E[2], f2, e); cfma(E[3], f3, e);
            } else {
                cfma(O[0], f0, e); cfma(O[1], f1, e); cfma(O[2], f2, e); cfma(O[3], f3, e);
            }
        }
#pragma unroll
        for (int q = 0; q < 4; ++q) {
            Hs[(q * 16 + mi) * 32 + c]      = make_float2(E[q].x + O[q].x, E[q].y + O[q].y);
            Hs[(q * 16 + mi) * 32 + c + 16] = make_float2(E[q].x - O[q].x, E[q].y - O[q].y);
        }
    }
    __syncthreads();
    {
        int c = t & 31, q = (t >> 5) & 3, ag = t >> 7;
        float E[8] = {}, O[8] = {};
#pragma unroll
        for (int mi = 0; mi < 16; ++mi) {
            float2 h = Hs[(q * 16 + mi) * 32 + c];
#pragma unroll
            for (int j = 0; j < 8; ++j) {
                float2 e = EBs[mi * 32 + ag * 8 + j];
                float re = h.x * e.x - h.y * e.y;
                if (mi & 1) O[j] += re; else E[j] += re;
            }
        }
        int bo = boq * 4 + q;
        float bv = bias[bo & 127];
        size_t base = ((size_t)(bo * 32 + k)) * 1024 + c;
#pragma unroll
        for (int j = 0; j < 8; ++j) {
            int a = ag * 8 + j;
            out[base + a * 32]        = E[j] + O[j] + bv;
            out[base + (a + 16) * 32] = E[j] - O[j] + bv;
        }
    }
}

// ---------------- stream/event fork-join (created at static init) -------------
static cudaStream_t g_s1 = 0;
static cudaEvent_t g_eP0 = 0, g_eTabF = 0, g_eA2 = 0, g_eTabD = 0;
static bool g_streamOK = false;
namespace {
struct StreamInit {
    StreamInit() {
        bool ok = (cudaStreamCreateWithFlags(&g_s1, cudaStreamNonBlocking) == cudaSuccess);
        ok = ok && (cudaEventCreateWithFlags(&g_eP0, cudaEventDisableTiming) == cudaSuccess);
        ok = ok && (cudaEventCreateWithFlags(&g_eTabF, cudaEventDisableTiming) == cudaSuccess);
        ok = ok && (cudaEventCreateWithFlags(&g_eA2, cudaEventDisableTiming) == cudaSuccess);
        ok = ok && (cudaEventCreateWithFlags(&g_eTabD, cudaEventDisableTiming) == cudaSuccess);
        g_streamOK = ok;
    }
};
static StreamInit g_streamInit;
}

// ---------------- launch ----------------
extern "C" void kernel_launch(void* const* d_in, const int* in_sizes, int n_in,
                              void* d_out, int out_size) {
    const float* x    = (const float*)d_in[0];
    const float* ker  = (const float*)d_in[1];
    const float* bias = (const float*)d_in[2];
    float* out = (float*)d_out;

    if (g_streamOK) {
        // main: p0 -> tabF -> b -> [wait a2] c -> [wait tabD] d -> ef
        // s1:   [wait p0] a1 -> [wait tabF] a2 -> tabD
        k_p0<<<1, 256>>>();
        cudaEventRecord(g_eP0, 0);
        cudaStreamWaitEvent(g_s1, g_eP0, 0);
        k_a1<<<512, 256, 0, g_s1>>>(x);
        k_tabF<<<126, 256>>>();
        cudaEventRecord(g_eTabF, 0);
        cudaStreamWaitEvent(g_s1, g_eTabF, 0);
        k_a2<<<dim3(16, 8), 256, 0, g_s1>>>();
        cudaEventRecord(g_eA2, g_s1);
        k_tabD<<<992, 256, 0, g_s1>>>();
        cudaEventRecord(g_eTabD, g_s1);
        k_b<<<128, 256>>>(ker);
        cudaStreamWaitEvent(0, g_eA2, 0);
        k_c<<<dim3(62, 2, 16), 256>>>();
        cudaStreamWaitEvent(0, g_eTabD, 0);
        k_d<<<dim3(4, 31, 16), 256>>>();
        k_ef<<<dim3(256, 32), 256>>>(out, bias);
    } else {
        k_p0<<<1, 256>>>();
        k_tabF<<<126, 256>>>();
        k_tabD<<<992, 256>>>();
        k_a1<<<512, 256>>>(x);
        k_a2<<<dim3(16, 8), 256>>>();
        k_b<<<128, 256>>>(ker);
        k_c<<<dim3(62, 2, 16), 256>>>();
        k_d<<<dim3(4, 31, 16), 256>>>();
        k_ef<<<dim3(256, 32), 256>>>(out, bias);
    }
    (void)in_sizes; (void)n_in; (void)out_size;
}